// round 14
// baseline (speedup 1.0000x reference)
#include <cuda_runtime.h>
#include <cuda_bf16.h>
#include <cstdint>

#define D        4096
#define NE       64
#define TOPK     8
#define NCAND    12
#define NTOK     16384
#define GAP_THR  5e-5f

#define BM2      128            // tokens per M-tile
#define CK       64             // K per chunk (64 bf16 = 128B = SW128 row)
#define NSEG     8              // K-split factor
#define CPS      (D / CK / NSEG)  // chunks per segment = 8
#define NTHR     256            // 8 warps

// Dynamic smem layout
#define OFF_TILES  512
#define A_BYTES    (BM2 * 128)                  // 16 KB per level
#define W_BYTES    (NE * 128)                   // 8 KB per level
#define BUF_BYTES  (2 * A_BYTES + 2 * W_BYTES)  // 48 KB per buffer
#define SMEM_TOTAL (OFF_TILES + 2 * BUF_BYTES)  // ~96.5 KB

// Scratch (device globals: no allocation allowed).
__device__ int g_cand[NTOK * NCAND];
__device__ int g_list[NTOK];
__device__ int g_cnt;
__device__ __align__(16) __nv_bfloat16 g_W2[2][NE * D];       // W split: hi, lo bf16
__device__ __align__(16) float g_part[NSEG * NTOK * NE];      // 32 MB partial scores

// ---------------- helpers ----------------
__device__ __forceinline__ uint32_t smem_u32(const void* p) {
    uint32_t a;
    asm("{ .reg .u64 t; cvta.to.shared.u64 t, %1; cvt.u32.u64 %0, t; }" : "=r"(a) : "l"(p));
    return a;
}
#define SWZ(off) ((off) ^ (((off) >> 3) & 0x70))

#define STS128(addr, r0, r1, r2, r3) \
    asm volatile("st.shared.v4.b32 [%0], {%1, %2, %3, %4};" \
                 :: "r"(addr), "r"(r0), "r"(r1), "r"(r2), "r"(r3) : "memory")

#define LDSM4(r, addr) \
    asm volatile("ldmatrix.sync.aligned.m8n8.x4.shared.b16 {%0,%1,%2,%3}, [%4];" \
        : "=r"((r)[0]), "=r"((r)[1]), "=r"((r)[2]), "=r"((r)[3]) : "r"(addr))

#define MMA16816(c, a, b0, b1) \
    asm volatile("mma.sync.aligned.m16n8k16.row.col.f32.bf16.bf16.f32 " \
        "{%0,%1,%2,%3}, {%4,%5,%6,%7}, {%8,%9}, {%0,%1,%2,%3};" \
        : "+f"((c)[0]), "+f"((c)[1]), "+f"((c)[2]), "+f"((c)[3]) \
        : "r"((a)[0]), "r"((a)[1]), "r"((a)[2]), "r"((a)[3]), "r"(b0), "r"(b1))

// 2-level bf16 split of a packed f32 pair.
__device__ __forceinline__ void split1(float a, float b, uint32_t& hi, uint32_t& lo) {
    __nv_bfloat162 h = __floats2bfloat162_rn(a, b);
    float ra = a - __bfloat162float(h.x);
    float rb = b - __bfloat162float(h.y);
    __nv_bfloat162 l = __floats2bfloat162_rn(ra, rb);
    hi = *reinterpret_cast<uint32_t*>(&h);
    lo = *reinterpret_cast<uint32_t*>(&l);
}

// Neumaier compensated add.
__device__ __forceinline__ void neum(float& s, float& c, float x) {
    float t = s + x;
    float z = (fabsf(s) >= fabsf(x)) ? ((s - t) + x) : ((x - t) + s);
    c += z;
    s = t;
}
// Exact TwoSum merge of two compensated pairs into (sa, ca).
__device__ __forceinline__ void merge_pair(float& sa, float& ca, float sb, float cb) {
    float t  = sa + sb;
    float bp = t - sa;
    float er = (sa - (t - bp)) + (sb - bp);
    sa = t;
    ca = ca + cb + er;
}

// prep: split W to hi/lo bf16 + reset flag counter (merged reset launch).
__global__ void prep_w_kernel(const float* __restrict__ W) {
    int i = blockIdx.x * 256 + threadIdx.x;
    if (i == 0) g_cnt = 0;
    if (i < NE * D) {
        float w = W[i];
        __nv_bfloat16 b0 = __float2bfloat16(w);
        float r1 = w - __bfloat162float(b0);
        __nv_bfloat16 b1 = __float2bfloat16(r1);
        g_W2[0][i] = b0;
        g_W2[1][i] = b1;
    }
}

// ---------------- router: partial GEMM over one K-segment ----------------
// grid (128, NSEG): x = M-tile, y = K-segment. Writes g_part[seg][token][col].
__global__ __launch_bounds__(NTHR, 1)
void router_kernel(const float* __restrict__ A)
{
    extern __shared__ char smem[];
    const uint32_t sb  = smem_u32(smem);
    const int tid = threadIdx.x;
    const int wid = tid >> 5;
    const int lid = tid & 31;
    const int m0  = blockIdx.x * BM2;
    const int seg = blockIdx.y;
    const int c0chunk = seg * CPS;

    // ---- producer mapping: thread = (token row, 32-element k-half) ----
    const int arow = tid >> 1;
    const int akin = (tid & 1) * 32;
    const float* Arow = A + (size_t)(m0 + arow) * D + akin;

    uint32_t aoff[4];
#pragma unroll
    for (int g = 0; g < 4; g++)
        aoff[g] = SWZ((uint32_t)arow * 128 + (uint32_t)(akin + 8 * g) * 2);

    // W: 2 levels x 64 rows x 8 16B-units = 1024 units over 256 threads (4 each)
    int      wlv[4], welem[4];
    uint32_t woff[4];
#pragma unroll
    for (int i = 0; i < 4; i++) {
        int u    = tid + 256 * i;
        wlv[i]   = u >> 9;
        int rem  = u & 511;
        int wrow = rem >> 3;
        int wgrp = rem & 7;
        welem[i] = wrow * D + wgrp * 8;
        woff[i]  = SWZ((uint32_t)wrow * 128 + (uint32_t)wgrp * 16);
    }

    // ---- compute mapping: warp owns rows 16*wid..16*wid+15, all 64 experts ----
    const int mrow = wid * 16;
    const uint32_t a_base = (uint32_t)(mrow + (lid & 15)) * 128 + (uint32_t)(lid >> 4) * 16;
    const int q = lid >> 3;
    const uint32_t w_base = (uint32_t)((q >> 1) * 8 + (lid & 7)) * 128 + (uint32_t)(q & 1) * 16;

    uint32_t a_sw[4], w_sw[4];
#pragma unroll
    for (int ks = 0; ks < 4; ks++) {
        a_sw[ks] = SWZ(a_base + ks * 32);   // K-advance BEFORE swizzle (no row-bit carry)
        w_sw[ks] = SWZ(w_base + ks * 32);
    }

    float acc[32];
#pragma unroll
    for (int i = 0; i < 32; i++) acc[i] = 0.f;

    // prefetch first chunk of this segment
    float4 pa[8];
    uint4  pw[4];
    {
        const int k0 = c0chunk * CK;
        const float4* ag = reinterpret_cast<const float4*>(Arow + k0);
#pragma unroll
        for (int j = 0; j < 8; j++) pa[j] = ag[j];
#pragma unroll
        for (int i = 0; i < 4; i++)
            pw[i] = *reinterpret_cast<const uint4*>(&g_W2[wlv[i]][(size_t)welem[i] + k0]);
    }

    for (int chunk = c0chunk; chunk < c0chunk + CPS; chunk++) {
        const int buf = chunk & 1;
        const uint32_t tb = sb + OFF_TILES + buf * BUF_BYTES;

        // ---- store prefetched chunk (A split hi/lo, W copy) ----
#pragma unroll
        for (int g = 0; g < 4; g++) {
            float4 x = pa[2 * g];
            float4 y = pa[2 * g + 1];
            uint32_t h[4], l[4];
            split1(x.x, x.y, h[0], l[0]);
            split1(x.z, x.w, h[1], l[1]);
            split1(y.x, y.y, h[2], l[2]);
            split1(y.z, y.w, h[3], l[3]);
            STS128(tb + 0 * A_BYTES + aoff[g], h[0], h[1], h[2], h[3]);
            STS128(tb + 1 * A_BYTES + aoff[g], l[0], l[1], l[2], l[3]);
        }
#pragma unroll
        for (int i = 0; i < 4; i++)
            STS128(tb + 2 * A_BYTES + (uint32_t)wlv[i] * W_BYTES + woff[i],
                   pw[i].x, pw[i].y, pw[i].z, pw[i].w);
        __syncthreads();

        // ---- prefetch next chunk ----
        if (chunk + 1 < c0chunk + CPS) {
            const int k0 = (chunk + 1) * CK;
            const float4* ag = reinterpret_cast<const float4*>(Arow + k0);
#pragma unroll
            for (int j = 0; j < 8; j++) pa[j] = ag[j];
#pragma unroll
            for (int i = 0; i < 4; i++)
                pw[i] = *reinterpret_cast<const uint4*>(&g_W2[wlv[i]][(size_t)welem[i] + k0]);
        }

        // ---- compute: 4 k16-steps x (2 A-ldsm + 8 B-ldsm + 24 mma) ----
        const uint32_t Ah = tb + 0 * A_BYTES;
        const uint32_t Al = tb + 1 * A_BYTES;
        const uint32_t Wh = tb + 2 * A_BYTES;
        const uint32_t Wl = Wh + W_BYTES;
#pragma unroll
        for (int ks = 0; ks < 4; ks++) {
            uint32_t ah[4], al[4];
            LDSM4(ah, Ah + a_sw[ks]);
            LDSM4(al, Al + a_sw[ks]);
#pragma unroll
            for (int p = 0; p < 4; p++) {
                uint32_t bh[4], bl[4];
                LDSM4(bh, Wh + p * 2048 + w_sw[ks]);
                LDSM4(bl, Wl + p * 2048 + w_sw[ks]);
                float* c0 = &acc[(2 * p) * 4];
                float* c1 = &acc[(2 * p + 1) * 4];
                MMA16816(c0, ah, bh[0], bh[1]);   // hi*hi
                MMA16816(c0, ah, bl[0], bl[1]);   // hi*lo
                MMA16816(c0, al, bh[0], bh[1]);   // lo*hi
                MMA16816(c1, ah, bh[2], bh[3]);
                MMA16816(c1, ah, bl[2], bl[3]);
                MMA16816(c1, al, bh[2], bh[3]);
            }
        }
        __syncthreads();   // also protects next iteration's buffer reuse
    }

    // ---- partials -> smem (pitch 65) -> coalesced STG.128 to g_part ----
    float* Ss = (float*)(smem + OFF_TILES);
    {
        const int col0 = (lid & 3) * 2;
        const int row  = mrow + (lid >> 2);
#pragma unroll
        for (int t = 0; t < 8; t++) {
            const int col = 8 * t + col0;
            Ss[row * 65 + col]           = acc[4 * t + 0];
            Ss[row * 65 + col + 1]       = acc[4 * t + 1];
            Ss[(row + 8) * 65 + col]     = acc[4 * t + 2];
            Ss[(row + 8) * 65 + col + 1] = acc[4 * t + 3];
        }
    }
    __syncthreads();
    {
        const int row  = tid >> 1;
        const int half = (tid & 1) * 32;
        float4* dst = reinterpret_cast<float4*>(
            g_part + ((size_t)seg * NTOK + m0 + row) * NE + half);
        const float* src = &Ss[row * 65 + half];
#pragma unroll
        for (int j = 0; j < 8; j++)
            dst[j] = make_float4(src[4 * j], src[4 * j + 1], src[4 * j + 2], src[4 * j + 3]);
    }
}

// ---------------- reduce + top-k: sum NSEG partials (fixed order), bias, flag ----------------
__global__ __launch_bounds__(128)
void reduce_topk_kernel(const float* __restrict__ bias,
                        float* __restrict__ out,
                        int write_idx)
{
    __shared__ float bs[NE];
    if (threadIdx.x < NE) bs[threadIdx.x] = bias[threadIdx.x];
    __syncthreads();

    const int g = blockIdx.x * 128 + threadIdx.x;

    float sc[NE];
#pragma unroll
    for (int s = 0; s < NSEG; s++) {
        const float4* p = reinterpret_cast<const float4*>(
            g_part + ((size_t)s * NTOK + g) * NE);
#pragma unroll
        for (int j = 0; j < NE / 4; j++) {
            float4 v = p[j];
            if (s == 0) {
                sc[4 * j] = v.x; sc[4 * j + 1] = v.y; sc[4 * j + 2] = v.z; sc[4 * j + 3] = v.w;
            } else {
                sc[4 * j] += v.x; sc[4 * j + 1] += v.y; sc[4 * j + 2] += v.z; sc[4 * j + 3] += v.w;
            }
        }
    }
#pragma unroll
    for (int e = 0; e < NE; e++) sc[e] += bs[e];

    const float NEG_INF = __int_as_float(0xff800000);
    float vals[NCAND];
    int   idxs[NCAND];
    unsigned long long used = 0ull;
#pragma unroll
    for (int r = 0; r < NCAND; r++) {
        float best = NEG_INF;
        int   bi   = 0;
#pragma unroll
        for (int e = 0; e < NE; e++) {
            const bool fr = !((used >> e) & 1ull);
            if (fr && sc[e] > best) { best = sc[e]; bi = e; }  // strict >: lowest index wins
        }
        used |= (1ull << bi);
        vals[r] = best;
        idxs[r] = bi;
    }

#pragma unroll
    for (int i = 0; i < NCAND; i++) g_cand[g * NCAND + i] = idxs[i];

    bool flagged = false;
#pragma unroll
    for (int i = 0; i < 9; i++)
        if (vals[i] - vals[i + 1] < GAP_THR) flagged = true;

    if (flagged) {
        int pos = atomicAdd(&g_cnt, 1);
        g_list[pos] = g;
    } else {
        const float mx = vals[0];
        float ex[TOPK];
        float s = 0.f;
#pragma unroll
        for (int i = 0; i < TOPK; i++) { ex[i] = expf(vals[i] - mx); s += ex[i]; }
        const float inv = 1.f / s;
#pragma unroll
        for (int i = 0; i < TOPK; i++)
            out[(size_t)g * TOPK + i] = ex[i] * inv;
        if (write_idx) {
#pragma unroll
            for (int i = 0; i < TOPK; i++)
                out[(size_t)NTOK * TOPK + (size_t)g * TOPK + i] = (float)idxs[i];
        }
    }
}

// ---------------- Phase 2: exact recomputation for near-tie tokens ----------------
// 4 independent Neumaier chains per lane (short dependency), TwoSum merge.
__global__ __launch_bounds__(128)
void refine_kernel(const float* __restrict__ A,
                   const float* __restrict__ W,
                   const float* __restrict__ bias,
                   float* __restrict__ out,
                   int write_idx)
{
    __shared__ float rv[NCAND];

    const int n  = g_cnt;
    const int wp = threadIdx.x >> 5;
    const int l  = threadIdx.x & 31;

    for (int it = blockIdx.x; it < n; it += gridDim.x) {
        const int tok = g_list[it];
        const float4* A4 = (const float4*)(A + (size_t)tok * D);

#pragma unroll
        for (int c = 0; c < 3; c++) {
            const int ci = wp * 3 + c;
            const int e  = g_cand[tok * NCAND + ci];
            const float4* W4 = (const float4*)(W + (size_t)e * D);

            float sx = 0.f, cx = 0.f, sy = 0.f, cy = 0.f;
            float sz = 0.f, cz = 0.f, sw2 = 0.f, cw = 0.f;
            for (int j = 0; j < D / 4 / 32; j++) {
                float4 a  = A4[l + 32 * j];
                float4 wv = W4[l + 32 * j];
                neum(sx, cx, a.x * wv.x);
                neum(sy, cy, a.y * wv.y);
                neum(sz, cz, a.z * wv.z);
                neum(sw2, cw, a.w * wv.w);
            }
            merge_pair(sx, cx, sy, cy);
            merge_pair(sz, cz, sw2, cw);
            merge_pair(sx, cx, sz, cz);

#pragma unroll
            for (int off = 16; off; off >>= 1) {
                float s2 = __shfl_down_sync(0xffffffffu, sx, off);
                float c2 = __shfl_down_sync(0xffffffffu, cx, off);
                merge_pair(sx, cx, s2, c2);
            }
            if (l == 0) rv[ci] = (sx + cx) + bias[e];
        }
        __syncthreads();

        if (threadIdx.x == 0) {
            float v[NCAND]; int id[NCAND]; bool usedv[NCAND];
#pragma unroll
            for (int i = 0; i < NCAND; i++) {
                v[i] = rv[i]; id[i] = g_cand[tok * NCAND + i]; usedv[i] = false;
            }
            float tv[TOPK]; int ti[TOPK];
#pragma unroll
            for (int i = 0; i < TOPK; i++) {
                int   bj = -1;
                float bv = 0.f;
                int   be = 1 << 30;
                for (int j = 0; j < NCAND; j++) {
                    if (usedv[j]) continue;
                    if (bj < 0 || v[j] > bv || (v[j] == bv && id[j] < be)) {
                        bj = j; bv = v[j]; be = id[j];
                    }
                }
                usedv[bj] = true;
                tv[i] = bv;
                ti[i] = be;
            }
            const float mx = tv[0];
            float ex[TOPK];
            float ss = 0.f;
#pragma unroll
            for (int i = 0; i < TOPK; i++) { ex[i] = expf(tv[i] - mx); ss += ex[i]; }
            const float inv = 1.f / ss;
#pragma unroll
            for (int i = 0; i < TOPK; i++)
                out[(size_t)tok * TOPK + i] = ex[i] * inv;
            if (write_idx) {
#pragma unroll
                for (int i = 0; i < TOPK; i++)
                    out[(size_t)NTOK * TOPK + (size_t)tok * TOPK + i] = (float)ti[i];
            }
        }
        __syncthreads();
    }
}

extern "C" void kernel_launch(void* const* d_in, const int* in_sizes, int n_in,
                              void* d_out, int out_size) {
    const float* A = (const float*)d_in[0];   // inputs [16384, 4096]
    const float* W = (const float*)d_in[1];   // W      [64, 4096]
    const float* b = (const float*)d_in[2];   // b      [64]
    float* out = (float*)d_out;

    const int write_idx = (out_size >= 2 * NTOK * TOPK) ? 1 : 0;

    cudaFuncSetAttribute(router_kernel, cudaFuncAttributeMaxDynamicSharedMemorySize, SMEM_TOTAL);

    prep_w_kernel<<<(NE * D + 255) / 256, 256>>>(W);
    router_kernel<<<dim3(NTOK / BM2, NSEG), NTHR, SMEM_TOTAL>>>(A);
    reduce_topk_kernel<<<NTOK / 128, 128>>>(b, out, write_idx);
    refine_kernel<<<64, 128>>>(A, W, b, out, write_idx);
}

// round 15
// speedup vs baseline: 1.2602x; 1.2602x over previous
#include <cuda_runtime.h>
#include <cuda_bf16.h>
#include <cstdint>

#define D        4096
#define NE       64
#define TOPK     8
#define NCAND    12
#define NTOK     16384
#define GAP_THR  5e-5f

#define BM2      128            // tokens per CTA
#define CK       64             // K per chunk (64 bf16 = 128B = SW128 row)
#define NCHUNK   (D / CK)       // 64
#define NTHR     256            // 8 warps

// Dynamic smem layout
#define OFF_BIAS   0
#define OFF_TILES  512
#define A_BYTES    (BM2 * 128)                  // 16 KB per level
#define W_BYTES    (NE * 128)                   // 8 KB per level
#define BUF_BYTES  (2 * A_BYTES + 2 * W_BYTES)  // 48 KB per buffer
#define SMEM_TOTAL (OFF_TILES + 2 * BUF_BYTES)  // ~96.5 KB

// Scratch (device globals: no allocation allowed).
__device__ int g_cand[NTOK * NCAND];
__device__ int g_list[NTOK];
__device__ int g_cnt;
__device__ __align__(16) __nv_bfloat16 g_W2[2][NE * D];   // W split: hi, lo bf16

// ---------------- helpers ----------------
__device__ __forceinline__ uint32_t smem_u32(const void* p) {
    uint32_t a;
    asm("{ .reg .u64 t; cvta.to.shared.u64 t, %1; cvt.u32.u64 %0, t; }" : "=r"(a) : "l"(p));
    return a;
}
#define SWZ(off) ((off) ^ (((off) >> 3) & 0x70))

#define STS128(addr, r0, r1, r2, r3) \
    asm volatile("st.shared.v4.b32 [%0], {%1, %2, %3, %4};" \
                 :: "r"(addr), "r"(r0), "r"(r1), "r"(r2), "r"(r3) : "memory")

#define LDSM4(r, addr) \
    asm volatile("ldmatrix.sync.aligned.m8n8.x4.shared.b16 {%0,%1,%2,%3}, [%4];" \
        : "=r"((r)[0]), "=r"((r)[1]), "=r"((r)[2]), "=r"((r)[3]) : "r"(addr))

#define MMA16816(c, a, b0, b1) \
    asm volatile("mma.sync.aligned.m16n8k16.row.col.f32.bf16.bf16.f32 " \
        "{%0,%1,%2,%3}, {%4,%5,%6,%7}, {%8,%9}, {%0,%1,%2,%3};" \
        : "+f"((c)[0]), "+f"((c)[1]), "+f"((c)[2]), "+f"((c)[3]) \
        : "r"((a)[0]), "r"((a)[1]), "r"((a)[2]), "r"((a)[3]), "r"(b0), "r"(b1))

// 2-level bf16 split of a packed f32 pair.
__device__ __forceinline__ void split1(float a, float b, uint32_t& hi, uint32_t& lo) {
    __nv_bfloat162 h = __floats2bfloat162_rn(a, b);
    float ra = a - __bfloat162float(h.x);
    float rb = b - __bfloat162float(h.y);
    __nv_bfloat162 l = __floats2bfloat162_rn(ra, rb);
    hi = *reinterpret_cast<uint32_t*>(&h);
    lo = *reinterpret_cast<uint32_t*>(&l);
}

// Neumaier compensated add.
__device__ __forceinline__ void neum(float& s, float& c, float x) {
    float t = s + x;
    float z = (fabsf(s) >= fabsf(x)) ? ((s - t) + x) : ((x - t) + s);
    c += z;
    s = t;
}
// Exact TwoSum merge of two compensated pairs into (sa, ca).
__device__ __forceinline__ void merge_pair(float& sa, float& ca, float sb, float cb) {
    float t  = sa + sb;
    float bp = t - sa;
    float er = (sa - (t - bp)) + (sb - bp);
    sa = t;
    ca = ca + cb + er;
}

// prep: split W to hi/lo bf16 + reset flag counter (merged reset launch).
__global__ void prep_w_kernel(const float* __restrict__ W) {
    int i = blockIdx.x * 256 + threadIdx.x;
    if (i == 0) g_cnt = 0;
    if (i < NE * D) {
        float w = W[i];
        __nv_bfloat16 b0 = __float2bfloat16(w);
        float r1 = w - __bfloat162float(b0);
        __nv_bfloat16 b1 = __float2bfloat16(r1);
        g_W2[0][i] = b0;
        g_W2[1][i] = b1;
    }
}

// ---------------- main router: mma.sync bf16-split GEMM + fused top-k ----------------
__global__ __launch_bounds__(NTHR, 1)
void router_kernel(const float* __restrict__ A,
                   const float* __restrict__ bias,
                   float* __restrict__ out,
                   int write_idx)
{
    extern __shared__ char smem[];
    const uint32_t sb  = smem_u32(smem);
    const int tid = threadIdx.x;
    const int wid = tid >> 5;
    const int lid = tid & 31;
    const int m0  = blockIdx.x * BM2;

    if (tid < NE) ((float*)(smem + OFF_BIAS))[tid] = bias[tid];

    // ---- producer mapping: thread = (token row, 32-element k-half) ----
    const int arow = tid >> 1;
    const int akin = (tid & 1) * 32;
    const float* Arow = A + (size_t)(m0 + arow) * D + akin;

    uint32_t aoff[4];
#pragma unroll
    for (int g = 0; g < 4; g++)
        aoff[g] = SWZ((uint32_t)arow * 128 + (uint32_t)(akin + 8 * g) * 2);

    // W: 2 levels x 64 rows x 8 16B-units = 1024 units over 256 threads (4 each)
    int      wlv[4], welem[4];
    uint32_t woff[4];
#pragma unroll
    for (int i = 0; i < 4; i++) {
        int u    = tid + 256 * i;
        wlv[i]   = u >> 9;
        int rem  = u & 511;
        int wrow = rem >> 3;
        int wgrp = rem & 7;
        welem[i] = wrow * D + wgrp * 8;
        woff[i]  = SWZ((uint32_t)wrow * 128 + (uint32_t)wgrp * 16);
    }

    // ---- compute mapping: warp owns rows 16*wid..16*wid+15, all 64 experts ----
    const int mrow = wid * 16;
    const uint32_t a_base = (uint32_t)(mrow + (lid & 15)) * 128 + (uint32_t)(lid >> 4) * 16;
    const int q = lid >> 3;
    const uint32_t w_base = (uint32_t)((q >> 1) * 8 + (lid & 7)) * 128 + (uint32_t)(q & 1) * 16;

    uint32_t a_sw[4], w_sw[4];
#pragma unroll
    for (int ks = 0; ks < 4; ks++) {
        a_sw[ks] = SWZ(a_base + ks * 32);   // K-advance BEFORE swizzle (no row-bit carry)
        w_sw[ks] = SWZ(w_base + ks * 32);
    }

    float acc[32];
#pragma unroll
    for (int i = 0; i < 32; i++) acc[i] = 0.f;

    // prefetch chunk 0
    float4 pa[8];
    uint4  pw[4];
    {
        const float4* ag = reinterpret_cast<const float4*>(Arow);
#pragma unroll
        for (int j = 0; j < 8; j++) pa[j] = ag[j];
#pragma unroll
        for (int i = 0; i < 4; i++)
            pw[i] = *reinterpret_cast<const uint4*>(&g_W2[wlv[i]][(size_t)welem[i]]);
    }

    for (int chunk = 0; chunk < NCHUNK; chunk++) {
        const int buf = chunk & 1;
        const uint32_t tb = sb + OFF_TILES + buf * BUF_BYTES;

        // ---- store prefetched chunk (A split to hi/lo, W pre-split copy) ----
#pragma unroll
        for (int g = 0; g < 4; g++) {
            float4 x = pa[2 * g];
            float4 y = pa[2 * g + 1];
            uint32_t h[4], l[4];
            split1(x.x, x.y, h[0], l[0]);
            split1(x.z, x.w, h[1], l[1]);
            split1(y.x, y.y, h[2], l[2]);
            split1(y.z, y.w, h[3], l[3]);
            STS128(tb + 0 * A_BYTES + aoff[g], h[0], h[1], h[2], h[3]);
            STS128(tb + 1 * A_BYTES + aoff[g], l[0], l[1], l[2], l[3]);
        }
#pragma unroll
        for (int i = 0; i < 4; i++)
            STS128(tb + 2 * A_BYTES + (uint32_t)wlv[i] * W_BYTES + woff[i],
                   pw[i].x, pw[i].y, pw[i].z, pw[i].w);
        __syncthreads();

        // ---- prefetch next chunk (overlaps compute) ----
        if (chunk + 1 < NCHUNK) {
            const int k0 = (chunk + 1) * CK;
            const float4* ag = reinterpret_cast<const float4*>(Arow + k0);
#pragma unroll
            for (int j = 0; j < 8; j++) pa[j] = ag[j];
#pragma unroll
            for (int i = 0; i < 4; i++)
                pw[i] = *reinterpret_cast<const uint4*>(&g_W2[wlv[i]][(size_t)welem[i] + k0]);
        }

        // ---- compute: 4 k16-steps x (2 A-ldsm + 8 B-ldsm + 24 mma) ----
        const uint32_t Ah = tb + 0 * A_BYTES;
        const uint32_t Al = tb + 1 * A_BYTES;
        const uint32_t Wh = tb + 2 * A_BYTES;
        const uint32_t Wl = Wh + W_BYTES;
#pragma unroll
        for (int ks = 0; ks < 4; ks++) {
            uint32_t ah[4], al[4];
            LDSM4(ah, Ah + a_sw[ks]);
            LDSM4(al, Al + a_sw[ks]);
#pragma unroll
            for (int p = 0; p < 4; p++) {
                uint32_t bh[4], bl[4];
                LDSM4(bh, Wh + p * 2048 + w_sw[ks]);
                LDSM4(bl, Wl + p * 2048 + w_sw[ks]);
                float* c0 = &acc[(2 * p) * 4];
                float* c1 = &acc[(2 * p + 1) * 4];
                MMA16816(c0, ah, bh[0], bh[1]);   // hi*hi
                MMA16816(c0, ah, bl[0], bl[1]);   // hi*lo
                MMA16816(c0, al, bh[0], bh[1]);   // lo*hi
                MMA16816(c1, ah, bh[2], bh[3]);
                MMA16816(c1, ah, bl[2], bl[3]);
                MMA16816(c1, al, bh[2], bh[3]);
            }
        }
        // Double buffer + one sync/iter is race-free: a warp reaches iter i+2's
        // store of buffer b only after passing iter i+1's barrier, which every
        // warp reaches only after finishing its iter-i compute on buffer b.
    }
    __syncthreads();

    // ---- scores -> smem (pitch 65), +bias ----
    float* Ss = (float*)(smem + OFF_TILES);
    const float* bs = (const float*)(smem + OFF_BIAS);
    {
        const int col0 = (lid & 3) * 2;
        const int row  = mrow + (lid >> 2);
#pragma unroll
        for (int t = 0; t < 8; t++) {
            const int col = 8 * t + col0;
            Ss[row * 65 + col]           = acc[4 * t + 0] + bs[col];
            Ss[row * 65 + col + 1]       = acc[4 * t + 1] + bs[col + 1];
            Ss[(row + 8) * 65 + col]     = acc[4 * t + 2] + bs[col];
            Ss[(row + 8) * 65 + col + 1] = acc[4 * t + 3] + bs[col + 1];
        }
    }
    __syncthreads();

    // ---- per-token top-12 (in registers, bitmask scan), flag near-ties ----
    if (tid < BM2) {
        const int g = m0 + tid;
        float sc[NE];
#pragma unroll
        for (int e = 0; e < NE; e++) sc[e] = Ss[tid * 65 + e];

        const float NEG_INF = __int_as_float(0xff800000);
        float vals[NCAND];
        int   idxs[NCAND];
        unsigned long long used = 0ull;
#pragma unroll
        for (int r = 0; r < NCAND; r++) {
            float best = NEG_INF;
            int   bi   = 0;
#pragma unroll
            for (int e = 0; e < NE; e++) {
                const bool fr = !((used >> e) & 1ull);
                if (fr && sc[e] > best) { best = sc[e]; bi = e; }  // strict >: lowest idx wins
            }
            used |= (1ull << bi);
            vals[r] = best;
            idxs[r] = bi;
        }

#pragma unroll
        for (int i = 0; i < NCAND; i++) g_cand[g * NCAND + i] = idxs[i];

        bool flagged = false;
#pragma unroll
        for (int i = 0; i < 9; i++)
            if (vals[i] - vals[i + 1] < GAP_THR) flagged = true;

        if (flagged) {
            int pos = atomicAdd(&g_cnt, 1);
            g_list[pos] = g;
        } else {
            const float mx = vals[0];
            float ex[TOPK];
            float s = 0.f;
#pragma unroll
            for (int i = 0; i < TOPK; i++) { ex[i] = expf(vals[i] - mx); s += ex[i]; }
            const float inv = 1.f / s;
            float4* po = reinterpret_cast<float4*>(out + (size_t)g * TOPK);
            po[0] = make_float4(ex[0] * inv, ex[1] * inv, ex[2] * inv, ex[3] * inv);
            po[1] = make_float4(ex[4] * inv, ex[5] * inv, ex[6] * inv, ex[7] * inv);
            if (write_idx) {
                float4* pi = reinterpret_cast<float4*>(out + (size_t)NTOK * TOPK + (size_t)g * TOPK);
                pi[0] = make_float4((float)idxs[0], (float)idxs[1], (float)idxs[2], (float)idxs[3]);
                pi[1] = make_float4((float)idxs[4], (float)idxs[5], (float)idxs[6], (float)idxs[7]);
            }
        }
    }
}

// ---------------- Phase 2: exact recomputation for near-tie tokens ----------------
// Grid 256 (latency-bound: blocks are the parallelism) + 4 independent Neumaier
// chains per lane, merged by exact TwoSum.
__global__ __launch_bounds__(128)
void refine_kernel(const float* __restrict__ A,
                   const float* __restrict__ W,
                   const float* __restrict__ bias,
                   float* __restrict__ out,
                   int write_idx)
{
    __shared__ float rv[NCAND];

    const int n  = g_cnt;
    const int wp = threadIdx.x >> 5;
    const int l  = threadIdx.x & 31;

    for (int it = blockIdx.x; it < n; it += gridDim.x) {
        const int tok = g_list[it];
        const float4* A4 = (const float4*)(A + (size_t)tok * D);

#pragma unroll
        for (int c = 0; c < 3; c++) {
            const int ci = wp * 3 + c;
            const int e  = g_cand[tok * NCAND + ci];
            const float4* W4 = (const float4*)(W + (size_t)e * D);

            float sx = 0.f, cx = 0.f, sy = 0.f, cy = 0.f;
            float sz = 0.f, cz = 0.f, sw2 = 0.f, cw = 0.f;
            for (int j = 0; j < D / 4 / 32; j++) {
                float4 a  = A4[l + 32 * j];
                float4 wv = W4[l + 32 * j];
                neum(sx, cx, a.x * wv.x);
                neum(sy, cy, a.y * wv.y);
                neum(sz, cz, a.z * wv.z);
                neum(sw2, cw, a.w * wv.w);
            }
            merge_pair(sx, cx, sy, cy);
            merge_pair(sz, cz, sw2, cw);
            merge_pair(sx, cx, sz, cz);

#pragma unroll
            for (int off = 16; off; off >>= 1) {
                float s2 = __shfl_down_sync(0xffffffffu, sx, off);
                float c2 = __shfl_down_sync(0xffffffffu, cx, off);
                merge_pair(sx, cx, s2, c2);
            }
            if (l == 0) rv[ci] = (sx + cx) + bias[e];
        }
        __syncthreads();

        if (threadIdx.x == 0) {
            float v[NCAND]; int id[NCAND]; bool usedv[NCAND];
#pragma unroll
            for (int i = 0; i < NCAND; i++) {
                v[i] = rv[i]; id[i] = g_cand[tok * NCAND + i]; usedv[i] = false;
            }
            float tv[TOPK]; int ti[TOPK];
#pragma unroll
            for (int i = 0; i < TOPK; i++) {
                int   bj = -1;
                float bv = 0.f;
                int   be = 1 << 30;
                for (int j = 0; j < NCAND; j++) {
                    if (usedv[j]) continue;
                    if (bj < 0 || v[j] > bv || (v[j] == bv && id[j] < be)) {
                        bj = j; bv = v[j]; be = id[j];
                    }
                }
                usedv[bj] = true;
                tv[i] = bv;
                ti[i] = be;
            }
            const float mx = tv[0];
            float ex[TOPK];
            float ss = 0.f;
#pragma unroll
            for (int i = 0; i < TOPK; i++) { ex[i] = expf(tv[i] - mx); ss += ex[i]; }
            const float inv = 1.f / ss;
#pragma unroll
            for (int i = 0; i < TOPK; i++)
                out[(size_t)tok * TOPK + i] = ex[i] * inv;
            if (write_idx) {
#pragma unroll
                for (int i = 0; i < TOPK; i++)
                    out[(size_t)NTOK * TOPK + (size_t)tok * TOPK + i] = (float)ti[i];
            }
        }
        __syncthreads();
    }
}

extern "C" void kernel_launch(void* const* d_in, const int* in_sizes, int n_in,
                              void* d_out, int out_size) {
    const float* A = (const float*)d_in[0];   // inputs [16384, 4096]
    const float* W = (const float*)d_in[1];   // W      [64, 4096]
    const float* b = (const float*)d_in[2];   // b      [64]
    float* out = (float*)d_out;

    const int write_idx = (out_size >= 2 * NTOK * TOPK) ? 1 : 0;

    cudaFuncSetAttribute(router_kernel, cudaFuncAttributeMaxDynamicSharedMemorySize, SMEM_TOTAL);

    prep_w_kernel<<<(NE * D + 255) / 256, 256>>>(W);
    router_kernel<<<NTOK / BM2, NTHR, SMEM_TOTAL>>>(A, b, out, write_idx);
    refine_kernel<<<256, 128>>>(A, W, b, out, write_idx);
}

// round 16
// speedup vs baseline: 1.2743x; 1.0112x over previous
#include <cuda_runtime.h>
#include <cuda_bf16.h>
#include <cstdint>

#define D        4096
#define NE       64
#define TOPK     8
#define NCAND    12
#define NTOK     16384
#define GAP_THR  5e-5f

#define BM2      128            // tokens per CTA
#define CK       64             // K per chunk (64 bf16 = 128B = SW128 row)
#define NCHUNK   (D / CK)       // 64
#define NTHR     256            // 8 warps

// Dynamic smem layout
#define OFF_BIAS   0
#define OFF_TILES  512
#define A_BYTES    (BM2 * 128)                  // 16 KB per level
#define W_BYTES    (NE * 128)                   // 8 KB per level
#define BUF_BYTES  (2 * A_BYTES + 2 * W_BYTES)  // 48 KB per buffer
#define SMEM_TOTAL (OFF_TILES + 2 * BUF_BYTES)  // ~96.5 KB

// Scratch (device globals: no allocation allowed).
__device__ int g_cand[NTOK * NCAND];
__device__ int g_list[NTOK];
__device__ int g_cnt;
__device__ __align__(16) __nv_bfloat16 g_W2[2][NE * D];   // W split: hi, lo bf16

// ---------------- helpers ----------------
__device__ __forceinline__ uint32_t smem_u32(const void* p) {
    uint32_t a;
    asm("{ .reg .u64 t; cvta.to.shared.u64 t, %1; cvt.u32.u64 %0, t; }" : "=r"(a) : "l"(p));
    return a;
}
#define SWZ(off) ((off) ^ (((off) >> 3) & 0x70))

#define STS128(addr, r0, r1, r2, r3) \
    asm volatile("st.shared.v4.b32 [%0], {%1, %2, %3, %4};" \
                 :: "r"(addr), "r"(r0), "r"(r1), "r"(r2), "r"(r3) : "memory")

#define LDSM4(r, addr) \
    asm volatile("ldmatrix.sync.aligned.m8n8.x4.shared.b16 {%0,%1,%2,%3}, [%4];" \
        : "=r"((r)[0]), "=r"((r)[1]), "=r"((r)[2]), "=r"((r)[3]) : "r"(addr))

#define MMA16816(c, a, b0, b1) \
    asm volatile("mma.sync.aligned.m16n8k16.row.col.f32.bf16.bf16.f32 " \
        "{%0,%1,%2,%3}, {%4,%5,%6,%7}, {%8,%9}, {%0,%1,%2,%3};" \
        : "+f"((c)[0]), "+f"((c)[1]), "+f"((c)[2]), "+f"((c)[3]) \
        : "r"((a)[0]), "r"((a)[1]), "r"((a)[2]), "r"((a)[3]), "r"(b0), "r"(b1))

// 2-level bf16 split of a packed f32 pair.
__device__ __forceinline__ void split1(float a, float b, uint32_t& hi, uint32_t& lo) {
    __nv_bfloat162 h = __floats2bfloat162_rn(a, b);
    float ra = a - __bfloat162float(h.x);
    float rb = b - __bfloat162float(h.y);
    __nv_bfloat162 l = __floats2bfloat162_rn(ra, rb);
    hi = *reinterpret_cast<uint32_t*>(&h);
    lo = *reinterpret_cast<uint32_t*>(&l);
}

// Neumaier compensated add.
__device__ __forceinline__ void neum(float& s, float& c, float x) {
    float t = s + x;
    float z = (fabsf(s) >= fabsf(x)) ? ((s - t) + x) : ((x - t) + s);
    c += z;
    s = t;
}
// Exact TwoSum merge of two compensated pairs into (sa, ca).
__device__ __forceinline__ void merge_pair(float& sa, float& ca, float sb, float cb) {
    float t  = sa + sb;
    float bp = t - sa;
    float er = (sa - (t - bp)) + (sb - bp);
    sa = t;
    ca = ca + cb + er;
}

// prep: split W to hi/lo bf16 + reset flag counter (merged reset launch).
__global__ void prep_w_kernel(const float* __restrict__ W) {
    int i = blockIdx.x * 256 + threadIdx.x;
    if (i == 0) g_cnt = 0;
    if (i < NE * D) {
        float w = W[i];
        __nv_bfloat16 b0 = __float2bfloat16(w);
        float r1 = w - __bfloat162float(b0);
        __nv_bfloat16 b1 = __float2bfloat16(r1);
        g_W2[0][i] = b0;
        g_W2[1][i] = b1;
    }
}

// ---------------- main router: mma.sync bf16-split GEMM + fused top-k ----------------
// Pipelined: iteration i computes buffer (i&1) while splitting/storing chunk i+1
// into buffer ((i+1)&1). Stores are sliced and interleaved between ks-steps so
// producer ALU/STS work fills MMA-pipe bubbles.
__global__ __launch_bounds__(NTHR, 1)
void router_kernel(const float* __restrict__ A,
                   const float* __restrict__ bias,
                   float* __restrict__ out,
                   int write_idx)
{
    extern __shared__ char smem[];
    const uint32_t sb  = smem_u32(smem);
    const int tid = threadIdx.x;
    const int wid = tid >> 5;
    const int lid = tid & 31;
    const int m0  = blockIdx.x * BM2;

    if (tid < NE) ((float*)(smem + OFF_BIAS))[tid] = bias[tid];

    // ---- producer mapping: thread = (token row, 32-element k-half) ----
    const int arow = tid >> 1;
    const int akin = (tid & 1) * 32;
    const float* Arow = A + (size_t)(m0 + arow) * D + akin;

    uint32_t aoff[4];
#pragma unroll
    for (int g = 0; g < 4; g++)
        aoff[g] = SWZ((uint32_t)arow * 128 + (uint32_t)(akin + 8 * g) * 2);

    // W: 2 levels x 64 rows x 8 16B-units = 1024 units over 256 threads (4 each)
    int      wlv[4], welem[4];
    uint32_t woff[4];
#pragma unroll
    for (int i = 0; i < 4; i++) {
        int u    = tid + 256 * i;
        wlv[i]   = u >> 9;
        int rem  = u & 511;
        int wrow = rem >> 3;
        int wgrp = rem & 7;
        welem[i] = wrow * D + wgrp * 8;
        woff[i]  = SWZ((uint32_t)wrow * 128 + (uint32_t)wgrp * 16);
    }

    // ---- compute mapping: warp owns rows 16*wid..16*wid+15, all 64 experts ----
    const int mrow = wid * 16;
    const uint32_t a_base = (uint32_t)(mrow + (lid & 15)) * 128 + (uint32_t)(lid >> 4) * 16;
    const int q = lid >> 3;
    const uint32_t w_base = (uint32_t)((q >> 1) * 8 + (lid & 7)) * 128 + (uint32_t)(q & 1) * 16;

    uint32_t a_sw[4], w_sw[4];
#pragma unroll
    for (int ks = 0; ks < 4; ks++) {
        a_sw[ks] = SWZ(a_base + ks * 32);   // K-advance BEFORE swizzle (no row-bit carry)
        w_sw[ks] = SWZ(w_base + ks * 32);
    }

    float acc[32];
#pragma unroll
    for (int i = 0; i < 32; i++) acc[i] = 0.f;

    float4 pa[8];
    uint4  pw[4];

    // ---- prologue: load + store chunk 0 into buf0, prefetch chunk 1 ----
    {
        const float4* ag = reinterpret_cast<const float4*>(Arow);
#pragma unroll
        for (int j = 0; j < 8; j++) pa[j] = ag[j];
#pragma unroll
        for (int i = 0; i < 4; i++)
            pw[i] = *reinterpret_cast<const uint4*>(&g_W2[wlv[i]][(size_t)welem[i]]);

        const uint32_t tb = sb + OFF_TILES;   // buf 0
#pragma unroll
        for (int g = 0; g < 4; g++) {
            float4 x = pa[2 * g];
            float4 y = pa[2 * g + 1];
            uint32_t h[4], l[4];
            split1(x.x, x.y, h[0], l[0]);
            split1(x.z, x.w, h[1], l[1]);
            split1(y.x, y.y, h[2], l[2]);
            split1(y.z, y.w, h[3], l[3]);
            STS128(tb + 0 * A_BYTES + aoff[g], h[0], h[1], h[2], h[3]);
            STS128(tb + 1 * A_BYTES + aoff[g], l[0], l[1], l[2], l[3]);
        }
#pragma unroll
        for (int i = 0; i < 4; i++)
            STS128(tb + 2 * A_BYTES + (uint32_t)wlv[i] * W_BYTES + woff[i],
                   pw[i].x, pw[i].y, pw[i].z, pw[i].w);

        // prefetch chunk 1
        const float4* ag1 = reinterpret_cast<const float4*>(Arow + CK);
#pragma unroll
        for (int j = 0; j < 8; j++) pa[j] = ag1[j];
#pragma unroll
        for (int i = 0; i < 4; i++)
            pw[i] = *reinterpret_cast<const uint4*>(&g_W2[wlv[i]][(size_t)welem[i] + CK]);
    }
    __syncthreads();

    for (int chunk = 0; chunk < NCHUNK; chunk++) {
        const int buf = chunk & 1;
        const uint32_t tb  = sb + OFF_TILES + buf * BUF_BYTES;          // compute from
        const uint32_t tbn = sb + OFF_TILES + (buf ^ 1) * BUF_BYTES;    // store into
        const bool hn = (chunk + 1 < NCHUNK);

        const uint32_t Ah = tb + 0 * A_BYTES;
        const uint32_t Al = tb + 1 * A_BYTES;
        const uint32_t Wh = tb + 2 * A_BYTES;
        const uint32_t Wl = Wh + W_BYTES;

        // 4 ks-steps; after each step's LDSMs+MMAs, emit one slice of the
        // next-chunk stores (4 split1 + 2-3 STS) to fill MMA-pipe bubbles.
#pragma unroll
        for (int ks = 0; ks < 4; ks++) {
            uint32_t ah[4], al[4];
            LDSM4(ah, Ah + a_sw[ks]);
            LDSM4(al, Al + a_sw[ks]);
#pragma unroll
            for (int p = 0; p < 4; p++) {
                uint32_t bh[4], bl[4];
                LDSM4(bh, Wh + p * 2048 + w_sw[ks]);
                LDSM4(bl, Wl + p * 2048 + w_sw[ks]);
                float* c0 = &acc[(2 * p) * 4];
                float* c1 = &acc[(2 * p + 1) * 4];
                MMA16816(c0, ah, bh[0], bh[1]);   // hi*hi
                MMA16816(c0, ah, bl[0], bl[1]);   // hi*lo
                MMA16816(c0, al, bh[0], bh[1]);   // lo*hi
                MMA16816(c1, ah, bh[2], bh[3]);
                MMA16816(c1, ah, bl[2], bl[3]);
                MMA16816(c1, al, bh[2], bh[3]);
            }
            // ---- store slice ks of chunk+1 into the other buffer ----
            if (hn) {
                float4 x = pa[2 * ks];
                float4 y = pa[2 * ks + 1];
                uint32_t h[4], l[4];
                split1(x.x, x.y, h[0], l[0]);
                split1(x.z, x.w, h[1], l[1]);
                split1(y.x, y.y, h[2], l[2]);
                split1(y.z, y.w, h[3], l[3]);
                STS128(tbn + 0 * A_BYTES + aoff[ks], h[0], h[1], h[2], h[3]);
                STS128(tbn + 1 * A_BYTES + aoff[ks], l[0], l[1], l[2], l[3]);
                STS128(tbn + 2 * A_BYTES + (uint32_t)wlv[ks] * W_BYTES + woff[ks],
                       pw[ks].x, pw[ks].y, pw[ks].z, pw[ks].w);
            }
        }

        // ---- prefetch chunk+2 into registers ----
        if (chunk + 2 < NCHUNK) {
            const int k0 = (chunk + 2) * CK;
            const float4* ag = reinterpret_cast<const float4*>(Arow + k0);
#pragma unroll
            for (int j = 0; j < 8; j++) pa[j] = ag[j];
#pragma unroll
            for (int i = 0; i < 4; i++)
                pw[i] = *reinterpret_cast<const uint4*>(&g_W2[wlv[i]][(size_t)welem[i] + k0]);
        }

        // One barrier per iteration provides both orderings:
        //  - stores of chunk i+1 (buf^1) complete before iter i+1 computes buf^1
        //  - computes of buf complete before iter i+1 stores chunk i+2 into buf
        __syncthreads();
    }

    // ---- scores -> smem (pitch 65), +bias ----
    float* Ss = (float*)(smem + OFF_TILES);
    const float* bs = (const float*)(smem + OFF_BIAS);
    {
        const int col0 = (lid & 3) * 2;
        const int row  = mrow + (lid >> 2);
#pragma unroll
        for (int t = 0; t < 8; t++) {
            const int col = 8 * t + col0;
            Ss[row * 65 + col]           = acc[4 * t + 0] + bs[col];
            Ss[row * 65 + col + 1]       = acc[4 * t + 1] + bs[col + 1];
            Ss[(row + 8) * 65 + col]     = acc[4 * t + 2] + bs[col];
            Ss[(row + 8) * 65 + col + 1] = acc[4 * t + 3] + bs[col + 1];
        }
    }
    __syncthreads();

    // ---- per-token top-12 (in registers, bitmask scan), flag near-ties ----
    if (tid < BM2) {
        const int g = m0 + tid;
        float sc[NE];
#pragma unroll
        for (int e = 0; e < NE; e++) sc[e] = Ss[tid * 65 + e];

        const float NEG_INF = __int_as_float(0xff800000);
        float vals[NCAND];
        int   idxs[NCAND];
        unsigned long long used = 0ull;
#pragma unroll
        for (int r = 0; r < NCAND; r++) {
            float best = NEG_INF;
            int   bi   = 0;
#pragma unroll
            for (int e = 0; e < NE; e++) {
                const bool fr = !((used >> e) & 1ull);
                if (fr && sc[e] > best) { best = sc[e]; bi = e; }  // strict >: lowest idx wins
            }
            used |= (1ull << bi);
            vals[r] = best;
            idxs[r] = bi;
        }

#pragma unroll
        for (int i = 0; i < NCAND; i++) g_cand[g * NCAND + i] = idxs[i];

        bool flagged = false;
#pragma unroll
        for (int i = 0; i < 9; i++)
            if (vals[i] - vals[i + 1] < GAP_THR) flagged = true;

        if (flagged) {
            int pos = atomicAdd(&g_cnt, 1);
            g_list[pos] = g;
        } else {
            const float mx = vals[0];
            float ex[TOPK];
            float s = 0.f;
#pragma unroll
            for (int i = 0; i < TOPK; i++) { ex[i] = expf(vals[i] - mx); s += ex[i]; }
            const float inv = 1.f / s;
            float4* po = reinterpret_cast<float4*>(out + (size_t)g * TOPK);
            po[0] = make_float4(ex[0] * inv, ex[1] * inv, ex[2] * inv, ex[3] * inv);
            po[1] = make_float4(ex[4] * inv, ex[5] * inv, ex[6] * inv, ex[7] * inv);
            if (write_idx) {
                float4* pi = reinterpret_cast<float4*>(out + (size_t)NTOK * TOPK + (size_t)g * TOPK);
                pi[0] = make_float4((float)idxs[0], (float)idxs[1], (float)idxs[2], (float)idxs[3]);
                pi[1] = make_float4((float)idxs[4], (float)idxs[5], (float)idxs[6], (float)idxs[7]);
            }
        }
    }
}

// ---------------- Phase 2: exact recomputation for near-tie tokens ----------------
// Grid 256 (latency-bound: blocks are the parallelism) + 4 independent Neumaier
// chains per lane, merged by exact TwoSum.
__global__ __launch_bounds__(128)
void refine_kernel(const float* __restrict__ A,
                   const float* __restrict__ W,
                   const float* __restrict__ bias,
                   float* __restrict__ out,
                   int write_idx)
{
    __shared__ float rv[NCAND];

    const int n  = g_cnt;
    const int wp = threadIdx.x >> 5;
    const int l  = threadIdx.x & 31;

    for (int it = blockIdx.x; it < n; it += gridDim.x) {
        const int tok = g_list[it];
        const float4* A4 = (const float4*)(A + (size_t)tok * D);

#pragma unroll
        for (int c = 0; c < 3; c++) {
            const int ci = wp * 3 + c;
            const int e  = g_cand[tok * NCAND + ci];
            const float4* W4 = (const float4*)(W + (size_t)e * D);

            float sx = 0.f, cx = 0.f, sy = 0.f, cy = 0.f;
            float sz = 0.f, cz = 0.f, sw2 = 0.f, cw = 0.f;
            for (int j = 0; j < D / 4 / 32; j++) {
                float4 a  = A4[l + 32 * j];
                float4 wv = W4[l + 32 * j];
                neum(sx, cx, a.x * wv.x);
                neum(sy, cy, a.y * wv.y);
                neum(sz, cz, a.z * wv.z);
                neum(sw2, cw, a.w * wv.w);
            }
            merge_pair(sx, cx, sy, cy);
            merge_pair(sz, cz, sw2, cw);
            merge_pair(sx, cx, sz, cz);

#pragma unroll
            for (int off = 16; off; off >>= 1) {
                float s2 = __shfl_down_sync(0xffffffffu, sx, off);
                float c2 = __shfl_down_sync(0xffffffffu, cx, off);
                merge_pair(sx, cx, s2, c2);
            }
            if (l == 0) rv[ci] = (sx + cx) + bias[e];
        }
        __syncthreads();

        if (threadIdx.x == 0) {
            float v[NCAND]; int id[NCAND]; bool usedv[NCAND];
#pragma unroll
            for (int i = 0; i < NCAND; i++) {
                v[i] = rv[i]; id[i] = g_cand[tok * NCAND + i]; usedv[i] = false;
            }
            float tv[TOPK]; int ti[TOPK];
#pragma unroll
            for (int i = 0; i < TOPK; i++) {
                int   bj = -1;
                float bv = 0.f;
                int   be = 1 << 30;
                for (int j = 0; j < NCAND; j++) {
                    if (usedv[j]) continue;
                    if (bj < 0 || v[j] > bv || (v[j] == bv && id[j] < be)) {
                        bj = j; bv = v[j]; be = id[j];
                    }
                }
                usedv[bj] = true;
                tv[i] = bv;
                ti[i] = be;
            }
            const float mx = tv[0];
            float ex[TOPK];
            float ss = 0.f;
#pragma unroll
            for (int i = 0; i < TOPK; i++) { ex[i] = expf(tv[i] - mx); ss += ex[i]; }
            const float inv = 1.f / ss;
#pragma unroll
            for (int i = 0; i < TOPK; i++)
                out[(size_t)tok * TOPK + i] = ex[i] * inv;
            if (write_idx) {
#pragma unroll
                for (int i = 0; i < TOPK; i++)
                    out[(size_t)NTOK * TOPK + (size_t)tok * TOPK + i] = (float)ti[i];
            }
        }
        __syncthreads();
    }
}

extern "C" void kernel_launch(void* const* d_in, const int* in_sizes, int n_in,
                              void* d_out, int out_size) {
    const float* A = (const float*)d_in[0];   // inputs [16384, 4096]
    const float* W = (const float*)d_in[1];   // W      [64, 4096]
    const float* b = (const float*)d_in[2];   // b      [64]
    float* out = (float*)d_out;

    const int write_idx = (out_size >= 2 * NTOK * TOPK) ? 1 : 0;

    cudaFuncSetAttribute(router_kernel, cudaFuncAttributeMaxDynamicSharedMemorySize, SMEM_TOTAL);

    prep_w_kernel<<<(NE * D + 255) / 256, 256>>>(W);
    router_kernel<<<NTOK / BM2, NTHR, SMEM_TOTAL>>>(A, b, out, write_idx);
    refine_kernel<<<256, 128>>>(A, W, b, out, write_idx);
}

// round 17
// speedup vs baseline: 1.4802x; 1.1615x over previous
#include <cuda_runtime.h>
#include <cuda_bf16.h>
#include <cstdint>

#define D        4096
#define NE       64
#define TOPK     8
#define NCAND    12
#define NTOK     16384
#define GAP_THR  5e-5f

#define BM2      64             // tokens per CTA (occupancy 2 -> 4 warps/SMSP)
#define CK       64             // K per chunk (64 bf16 = 128B = SW128 row)
#define NCHUNK   (D / CK)       // 64
#define NTHR     256            // 8 warps: each 16 rows x 32 experts

// Dynamic smem layout
#define OFF_BIAS   0
#define OFF_TILES  512
#define A_BYTES    (BM2 * 128)                  // 8 KB per level
#define W_BYTES    (NE * 128)                   // 8 KB per level
#define BUF_BYTES  (2 * A_BYTES + 2 * W_BYTES)  // 32 KB per buffer
#define SMEM_TOTAL (OFF_TILES + 2 * BUF_BYTES)  // 64.5 KB -> 2 CTAs/SM

// Scratch (device globals: no allocation allowed).
__device__ int g_cand[NTOK * NCAND];
__device__ int g_list[NTOK];
__device__ int g_cnt;
__device__ __align__(16) __nv_bfloat16 g_W2[2][NE * D];   // W split: hi, lo bf16

// ---------------- helpers ----------------
__device__ __forceinline__ uint32_t smem_u32(const void* p) {
    uint32_t a;
    asm("{ .reg .u64 t; cvta.to.shared.u64 t, %1; cvt.u32.u64 %0, t; }" : "=r"(a) : "l"(p));
    return a;
}
#define SWZ(off) ((off) ^ (((off) >> 3) & 0x70))

#define STS128(addr, r0, r1, r2, r3) \
    asm volatile("st.shared.v4.b32 [%0], {%1, %2, %3, %4};" \
                 :: "r"(addr), "r"(r0), "r"(r1), "r"(r2), "r"(r3) : "memory")

#define LDSM4(r, addr) \
    asm volatile("ldmatrix.sync.aligned.m8n8.x4.shared.b16 {%0,%1,%2,%3}, [%4];" \
        : "=r"((r)[0]), "=r"((r)[1]), "=r"((r)[2]), "=r"((r)[3]) : "r"(addr))

#define MMA16816(c, a, b0, b1) \
    asm volatile("mma.sync.aligned.m16n8k16.row.col.f32.bf16.bf16.f32 " \
        "{%0,%1,%2,%3}, {%4,%5,%6,%7}, {%8,%9}, {%0,%1,%2,%3};" \
        : "+f"((c)[0]), "+f"((c)[1]), "+f"((c)[2]), "+f"((c)[3]) \
        : "r"((a)[0]), "r"((a)[1]), "r"((a)[2]), "r"((a)[3]), "r"(b0), "r"(b1))

// 2-level bf16 split of a packed f32 pair.
__device__ __forceinline__ void split1(float a, float b, uint32_t& hi, uint32_t& lo) {
    __nv_bfloat162 h = __floats2bfloat162_rn(a, b);
    float ra = a - __bfloat162float(h.x);
    float rb = b - __bfloat162float(h.y);
    __nv_bfloat162 l = __floats2bfloat162_rn(ra, rb);
    hi = *reinterpret_cast<uint32_t*>(&h);
    lo = *reinterpret_cast<uint32_t*>(&l);
}

// Neumaier compensated add.
__device__ __forceinline__ void neum(float& s, float& c, float x) {
    float t = s + x;
    float z = (fabsf(s) >= fabsf(x)) ? ((s - t) + x) : ((x - t) + s);
    c += z;
    s = t;
}
// Exact TwoSum merge of two compensated pairs into (sa, ca).
__device__ __forceinline__ void merge_pair(float& sa, float& ca, float sb, float cb) {
    float t  = sa + sb;
    float bp = t - sa;
    float er = (sa - (t - bp)) + (sb - bp);
    sa = t;
    ca = ca + cb + er;
}

// prep: split W to hi/lo bf16 + reset flag counter.
__global__ void prep_w_kernel(const float* __restrict__ W) {
    int i = blockIdx.x * 256 + threadIdx.x;
    if (i == 0) g_cnt = 0;
    if (i < NE * D) {
        float w = W[i];
        __nv_bfloat16 b0 = __float2bfloat16(w);
        float r1 = w - __bfloat162float(b0);
        __nv_bfloat16 b1 = __float2bfloat16(r1);
        g_W2[0][i] = b0;
        g_W2[1][i] = b1;
    }
}

// ---------------- main router: mma.sync bf16-split GEMM + fused top-k ----------------
// 64 tokens/CTA, occupancy 2 (4 warps/SMSP) for MMA-pipe latency hiding.
// Pipelined: iteration i computes buffer (i&1) while storing chunk i+1 into
// buffer ((i+1)&1), slices interleaved between ks-steps.
__global__ __launch_bounds__(NTHR, 2)
void router_kernel(const float* __restrict__ A,
                   const float* __restrict__ bias,
                   float* __restrict__ out,
                   int write_idx)
{
    extern __shared__ char smem[];
    const uint32_t sb  = smem_u32(smem);
    const int tid = threadIdx.x;
    const int wid = tid >> 5;
    const int lid = tid & 31;
    const int m0  = blockIdx.x * BM2;

    if (tid < NE) ((float*)(smem + OFF_BIAS))[tid] = bias[tid];

    // ---- producer mapping: thread = (token row, 16-element k-quarter) ----
    const int arow = tid >> 2;            // 0..63
    const int akin = (tid & 3) * 16;      // k offset within chunk
    const float* Arow = A + (size_t)(m0 + arow) * D + akin;

    uint32_t aoff[2];
#pragma unroll
    for (int g = 0; g < 2; g++)
        aoff[g] = SWZ((uint32_t)arow * 128 + (uint32_t)(akin + 8 * g) * 2);

    // W: 2 levels x 64 rows x 8 16B-units = 1024 units over 256 threads (4 each)
    int      wlv[4], welem[4];
    uint32_t woff[4];
#pragma unroll
    for (int i = 0; i < 4; i++) {
        int u    = tid + 256 * i;
        wlv[i]   = u >> 9;
        int rem  = u & 511;
        int wrow = rem >> 3;
        int wgrp = rem & 7;
        welem[i] = wrow * D + wgrp * 8;
        woff[i]  = SWZ((uint32_t)wrow * 128 + (uint32_t)wgrp * 16);
    }

    // ---- compute mapping: warp = (row group, expert half) ----
    const int mrow  = (wid & 3) * 16;     // rows mrow..mrow+15
    const int nhalf = wid >> 2;           // experts nhalf*32..+31
    const uint32_t a_base = (uint32_t)(mrow + (lid & 15)) * 128 + (uint32_t)(lid >> 4) * 16;
    const int q = lid >> 3;
    const uint32_t w_base = (uint32_t)((q >> 1) * 8 + (lid & 7)) * 128 + (uint32_t)(q & 1) * 16;

    uint32_t a_sw[4], w_sw[4];
#pragma unroll
    for (int ks = 0; ks < 4; ks++) {
        a_sw[ks] = SWZ(a_base + ks * 32);   // K-advance BEFORE swizzle (no row-bit carry)
        w_sw[ks] = SWZ(w_base + ks * 32);
    }

    float acc[16];
#pragma unroll
    for (int i = 0; i < 16; i++) acc[i] = 0.f;

    float4 pa[4];
    uint4  pw[4];

    // ---- prologue: load + store chunk 0 into buf0, prefetch chunk 1 ----
    {
        const float4* ag = reinterpret_cast<const float4*>(Arow);
#pragma unroll
        for (int j = 0; j < 4; j++) pa[j] = ag[j];
#pragma unroll
        for (int i = 0; i < 4; i++)
            pw[i] = *reinterpret_cast<const uint4*>(&g_W2[wlv[i]][(size_t)welem[i]]);

        const uint32_t tb = sb + OFF_TILES;   // buf 0
#pragma unroll
        for (int g = 0; g < 2; g++) {
            float4 x = pa[2 * g];
            float4 y = pa[2 * g + 1];
            uint32_t h[4], l[4];
            split1(x.x, x.y, h[0], l[0]);
            split1(x.z, x.w, h[1], l[1]);
            split1(y.x, y.y, h[2], l[2]);
            split1(y.z, y.w, h[3], l[3]);
            STS128(tb + 0 * A_BYTES + aoff[g], h[0], h[1], h[2], h[3]);
            STS128(tb + 1 * A_BYTES + aoff[g], l[0], l[1], l[2], l[3]);
        }
#pragma unroll
        for (int i = 0; i < 4; i++)
            STS128(tb + 2 * A_BYTES + (uint32_t)wlv[i] * W_BYTES + woff[i],
                   pw[i].x, pw[i].y, pw[i].z, pw[i].w);

        const float4* ag1 = reinterpret_cast<const float4*>(Arow + CK);
#pragma unroll
        for (int j = 0; j < 4; j++) pa[j] = ag1[j];
#pragma unroll
        for (int i = 0; i < 4; i++)
            pw[i] = *reinterpret_cast<const uint4*>(&g_W2[wlv[i]][(size_t)welem[i] + CK]);
    }
    __syncthreads();

    for (int chunk = 0; chunk < NCHUNK; chunk++) {
        const int buf = chunk & 1;
        const uint32_t tb  = sb + OFF_TILES + buf * BUF_BYTES;          // compute from
        const uint32_t tbn = sb + OFF_TILES + (buf ^ 1) * BUF_BYTES;    // store into
        const bool hn = (chunk + 1 < NCHUNK);

        const uint32_t Ah = tb + 0 * A_BYTES;
        const uint32_t Al = tb + 1 * A_BYTES;
        const uint32_t Wh = tb + 2 * A_BYTES;
        const uint32_t Wl = Wh + W_BYTES;

#pragma unroll
        for (int ks = 0; ks < 4; ks++) {
            uint32_t ah[4], al[4];
            LDSM4(ah, Ah + a_sw[ks]);
            LDSM4(al, Al + a_sw[ks]);
#pragma unroll
            for (int p = 0; p < 2; p++) {
                // 16-expert group index = nhalf*2 + p; stride 2048 B (16 rows)
                const uint32_t wgoff = (uint32_t)(nhalf * 2 + p) * 2048;
                uint32_t bh[4], bl[4];
                LDSM4(bh, Wh + wgoff + w_sw[ks]);
                LDSM4(bl, Wl + wgoff + w_sw[ks]);
                float* c0 = &acc[(2 * p) * 4];
                float* c1 = &acc[(2 * p + 1) * 4];
                MMA16816(c0, ah, bh[0], bh[1]);   // hi*hi
                MMA16816(c0, ah, bl[0], bl[1]);   // hi*lo
                MMA16816(c0, al, bh[0], bh[1]);   // lo*hi
                MMA16816(c1, ah, bh[2], bh[3]);
                MMA16816(c1, ah, bl[2], bl[3]);
                MMA16816(c1, al, bh[2], bh[3]);
            }
            // ---- store slices of chunk+1 into the other buffer ----
            if (hn) {
                if (ks < 2) {
                    float4 x = pa[2 * ks];
                    float4 y = pa[2 * ks + 1];
                    uint32_t h[4], l[4];
                    split1(x.x, x.y, h[0], l[0]);
                    split1(x.z, x.w, h[1], l[1]);
                    split1(y.x, y.y, h[2], l[2]);
                    split1(y.z, y.w, h[3], l[3]);
                    STS128(tbn + 0 * A_BYTES + aoff[ks], h[0], h[1], h[2], h[3]);
                    STS128(tbn + 1 * A_BYTES + aoff[ks], l[0], l[1], l[2], l[3]);
                }
                STS128(tbn + 2 * A_BYTES + (uint32_t)wlv[ks] * W_BYTES + woff[ks],
                       pw[ks].x, pw[ks].y, pw[ks].z, pw[ks].w);
            }
        }

        // ---- prefetch chunk+2 into registers ----
        if (chunk + 2 < NCHUNK) {
            const int k0 = (chunk + 2) * CK;
            const float4* ag = reinterpret_cast<const float4*>(Arow + k0);
#pragma unroll
            for (int j = 0; j < 4; j++) pa[j] = ag[j];
#pragma unroll
            for (int i = 0; i < 4; i++)
                pw[i] = *reinterpret_cast<const uint4*>(&g_W2[wlv[i]][(size_t)welem[i] + k0]);
        }

        __syncthreads();   // orders buf^1 stores before its compute, buf compute before reuse
    }

    // ---- scores -> smem (pitch 65), +bias ----
    float* Ss = (float*)(smem + OFF_TILES);
    const float* bs = (const float*)(smem + OFF_BIAS);
    {
        const int col0 = (lid & 3) * 2;
        const int row  = mrow + (lid >> 2);
#pragma unroll
        for (int t = 0; t < 4; t++) {
            const int col = nhalf * 32 + 8 * t + col0;
            Ss[row * 65 + col]           = acc[4 * t + 0] + bs[col];
            Ss[row * 65 + col + 1]       = acc[4 * t + 1] + bs[col + 1];
            Ss[(row + 8) * 65 + col]     = acc[4 * t + 2] + bs[col];
            Ss[(row + 8) * 65 + col + 1] = acc[4 * t + 3] + bs[col + 1];
        }
    }
    __syncthreads();

    // ---- per-token top-12 (in registers, bitmask scan), flag near-ties ----
    if (tid < BM2) {
        const int g = m0 + tid;
        float sc[NE];
#pragma unroll
        for (int e = 0; e < NE; e++) sc[e] = Ss[tid * 65 + e];

        const float NEG_INF = __int_as_float(0xff800000);
        float vals[NCAND];
        int   idxs[NCAND];
        unsigned long long used = 0ull;
#pragma unroll
        for (int r = 0; r < NCAND; r++) {
            float best = NEG_INF;
            int   bi   = 0;
#pragma unroll
            for (int e = 0; e < NE; e++) {
                const bool fr = !((used >> e) & 1ull);
                if (fr && sc[e] > best) { best = sc[e]; bi = e; }  // strict >: lowest idx wins
            }
            used |= (1ull << bi);
            vals[r] = best;
            idxs[r] = bi;
        }

#pragma unroll
        for (int i = 0; i < NCAND; i++) g_cand[g * NCAND + i] = idxs[i];

        bool flagged = false;
#pragma unroll
        for (int i = 0; i < 9; i++)
            if (vals[i] - vals[i + 1] < GAP_THR) flagged = true;

        if (flagged) {
            int pos = atomicAdd(&g_cnt, 1);
            g_list[pos] = g;
        } else {
            const float mx = vals[0];
            float ex[TOPK];
            float s = 0.f;
#pragma unroll
            for (int i = 0; i < TOPK; i++) { ex[i] = expf(vals[i] - mx); s += ex[i]; }
            const float inv = 1.f / s;
            float4* po = reinterpret_cast<float4*>(out + (size_t)g * TOPK);
            po[0] = make_float4(ex[0] * inv, ex[1] * inv, ex[2] * inv, ex[3] * inv);
            po[1] = make_float4(ex[4] * inv, ex[5] * inv, ex[6] * inv, ex[7] * inv);
            if (write_idx) {
                float4* pi = reinterpret_cast<float4*>(out + (size_t)NTOK * TOPK + (size_t)g * TOPK);
                pi[0] = make_float4((float)idxs[0], (float)idxs[1], (float)idxs[2], (float)idxs[3]);
                pi[1] = make_float4((float)idxs[4], (float)idxs[5], (float)idxs[6], (float)idxs[7]);
            }
        }
    }
}

// ---------------- Phase 2: exact recomputation for near-tie tokens ----------------
__global__ __launch_bounds__(128)
void refine_kernel(const float* __restrict__ A,
                   const float* __restrict__ W,
                   const float* __restrict__ bias,
                   float* __restrict__ out,
                   int write_idx)
{
    __shared__ float rv[NCAND];

    const int n  = g_cnt;
    const int wp = threadIdx.x >> 5;
    const int l  = threadIdx.x & 31;

    for (int it = blockIdx.x; it < n; it += gridDim.x) {
        const int tok = g_list[it];
        const float4* A4 = (const float4*)(A + (size_t)tok * D);

#pragma unroll
        for (int c = 0; c < 3; c++) {
            const int ci = wp * 3 + c;
            const int e  = g_cand[tok * NCAND + ci];
            const float4* W4 = (const float4*)(W + (size_t)e * D);

            float sx = 0.f, cx = 0.f, sy = 0.f, cy = 0.f;
            float sz = 0.f, cz = 0.f, sw2 = 0.f, cw = 0.f;
            for (int j = 0; j < D / 4 / 32; j++) {
                float4 a  = A4[l + 32 * j];
                float4 wv = W4[l + 32 * j];
                neum(sx, cx, a.x * wv.x);
                neum(sy, cy, a.y * wv.y);
                neum(sz, cz, a.z * wv.z);
                neum(sw2, cw, a.w * wv.w);
            }
            merge_pair(sx, cx, sy, cy);
            merge_pair(sz, cz, sw2, cw);
            merge_pair(sx, cx, sz, cz);

#pragma unroll
            for (int off = 16; off; off >>= 1) {
                float s2 = __shfl_down_sync(0xffffffffu, sx, off);
                float c2 = __shfl_down_sync(0xffffffffu, cx, off);
                merge_pair(sx, cx, s2, c2);
            }
            if (l == 0) rv[ci] = (sx + cx) + bias[e];
        }
        __syncthreads();

        if (threadIdx.x == 0) {
            float v[NCAND]; int id[NCAND]; bool usedv[NCAND];
#pragma unroll
            for (int i = 0; i < NCAND; i++) {
                v[i] = rv[i]; id[i] = g_cand[tok * NCAND + i]; usedv[i] = false;
            }
            float tv[TOPK]; int ti[TOPK];
#pragma unroll
            for (int i = 0; i < TOPK; i++) {
                int   bj = -1;
                float bv = 0.f;
                int   be = 1 << 30;
                for (int j = 0; j < NCAND; j++) {
                    if (usedv[j]) continue;
                    if (bj < 0 || v[j] > bv || (v[j] == bv && id[j] < be)) {
                        bj = j; bv = v[j]; be = id[j];
                    }
                }
                usedv[bj] = true;
                tv[i] = bv;
                ti[i] = be;
            }
            const float mx = tv[0];
            float ex[TOPK];
            float ss = 0.f;
#pragma unroll
            for (int i = 0; i < TOPK; i++) { ex[i] = expf(tv[i] - mx); ss += ex[i]; }
            const float inv = 1.f / ss;
#pragma unroll
            for (int i = 0; i < TOPK; i++)
                out[(size_t)tok * TOPK + i] = ex[i] * inv;
            if (write_idx) {
#pragma unroll
                for (int i = 0; i < TOPK; i++)
                    out[(size_t)NTOK * TOPK + (size_t)tok * TOPK + i] = (float)ti[i];
            }
        }
        __syncthreads();
    }
}

extern "C" void kernel_launch(void* const* d_in, const int* in_sizes, int n_in,
                              void* d_out, int out_size) {
    const float* A = (const float*)d_in[0];   // inputs [16384, 4096]
    const float* W = (const float*)d_in[1];   // W      [64, 4096]
    const float* b = (const float*)d_in[2];   // b      [64]
    float* out = (float*)d_out;

    const int write_idx = (out_size >= 2 * NTOK * TOPK) ? 1 : 0;

    cudaFuncSetAttribute(router_kernel, cudaFuncAttributeMaxDynamicSharedMemorySize, SMEM_TOTAL);

    prep_w_kernel<<<(NE * D + 255) / 256, 256>>>(W);
    router_kernel<<<NTOK / BM2, NTHR, SMEM_TOTAL>>>(A, b, out, write_idx);
    refine_kernel<<<256, 128>>>(A, W, b, out, write_idx);
}